// round 3
// baseline (speedup 1.0000x reference)
#include <cuda_runtime.h>
#include <math.h>

#define Bb 64
#define Tt 512
#define INN 1024
#define Hh 1024

#define NB 128      // persistent blocks (1/SM, co-resident on 148+ SMs)
#define TPB 384     // 12 warps: warp -> (gate g = w/4, batch-quarter bq = w%4)

typedef unsigned long long ull;

// ---------------- scratch (device globals; no allocation allowed) ----------------
__device__ float g_pre[4ull * Tt * Bb * Hh];     // [gate][t][b][h]  (512 MB)
__device__ float ct_buf[2][Bb * Hh];             // ping-pong cell state
__device__ unsigned g_bar = 0;                   // grid barrier counter

// ---------------- fp32x2 packed helpers (FFMA2 = full-rate fp32 on sm_103a) ------
__device__ __forceinline__ ull pk2(float lo, float hi) {
    ull r; asm("mov.b64 %0, {%1,%2};" : "=l"(r) : "f"(lo), "f"(hi)); return r;
}
__device__ __forceinline__ void unpk2(ull v, float& lo, float& hi) {
    asm("mov.b64 {%0,%1}, %2;" : "=f"(lo), "=f"(hi) : "l"(v));
}
__device__ __forceinline__ void fma2(ull& d, ull a, ull b) {
    asm("fma.rn.f32x2 %0, %1, %2, %3;" : "=l"(d) : "l"(a), "l"(b), "l"(d));
}

// ---------------- init: cell state from c0 + barrier reset ----------------
__global__ void init_kernel(const float* __restrict__ c0) {
    int i = blockIdx.x * 256 + threadIdx.x;  // 65536 total
    ct_buf[0][i] = c0[i & (Hh - 1)];
    if (i == 0) g_bar = 0;
}

// ---------------- input projections: g_pre[gate][t][b][h] = x @ Wx^T + bias -----
__global__ __launch_bounds__(256) void proj_kernel(
    const float* __restrict__ x,
    const float* __restrict__ Wf, const float* __restrict__ Wi,
    const float* __restrict__ Wo, const float* __restrict__ Wc,
    const float* __restrict__ bf, const float* __restrict__ bi,
    const float* __restrict__ bo, const float* __restrict__ bc) {
    __shared__ float As[8][128];
    __shared__ float Bs[8][128];

    int gate = blockIdx.y >> 3;
    int n0 = (blockIdx.y & 7) * 128;
    int m0 = blockIdx.x * 128;
    const float* W    = (gate == 0) ? Wf : (gate == 1) ? Wi : (gate == 2) ? Wo : Wc;
    const float* bias = (gate == 0) ? bf : (gate == 1) ? bi : (gate == 2) ? bo : bc;

    int tid = threadIdx.x;
    int tx = tid & 15;   // n dir (x8)
    int ty = tid >> 4;   // m dir (x8)
    int lr = tid >> 1;
    int lc = (tid & 1) * 4;
    const float* Ag = x + (size_t)(m0 + lr) * INN + lc;
    const float* Bg = W + (size_t)(n0 + lr) * INN + lc;

    ull acc2[8][4];
#pragma unroll
    for (int i = 0; i < 8; i++)
#pragma unroll
        for (int j = 0; j < 4; j++) acc2[i][j] = 0ull;

    for (int k0 = 0; k0 < INN; k0 += 8) {
        float4 av = *(const float4*)(Ag + k0);
        float4 bv = *(const float4*)(Bg + k0);
        As[lc + 0][lr] = av.x; As[lc + 1][lr] = av.y;
        As[lc + 2][lr] = av.z; As[lc + 3][lr] = av.w;
        Bs[lc + 0][lr] = bv.x; Bs[lc + 1][lr] = bv.y;
        Bs[lc + 2][lr] = bv.z; Bs[lc + 3][lr] = bv.w;
        __syncthreads();
#pragma unroll
        for (int kk = 0; kk < 8; kk++) {
            float4 a0 = *(const float4*)&As[kk][ty * 8];
            float4 a1 = *(const float4*)&As[kk][ty * 8 + 4];
            float a[8] = {a0.x, a0.y, a0.z, a0.w, a1.x, a1.y, a1.z, a1.w};
            float4 b0 = *(const float4*)&Bs[kk][tx * 8];
            float4 b1 = *(const float4*)&Bs[kk][tx * 8 + 4];
            ull bp[4] = {pk2(b0.x, b0.y), pk2(b0.z, b0.w),
                         pk2(b1.x, b1.y), pk2(b1.z, b1.w)};
#pragma unroll
            for (int i = 0; i < 8; i++) {
                ull ap = pk2(a[i], a[i]);
#pragma unroll
                for (int j = 0; j < 4; j++) fma2(acc2[i][j], ap, bp[j]);
            }
        }
        __syncthreads();
    }

#pragma unroll
    for (int i = 0; i < 8; i++) {
        int r = m0 + ty * 8 + i;
        int b_ = r >> 9;         // T = 512
        int t_ = r & (Tt - 1);
        float* dst = g_pre + (((size_t)gate * Tt + t_) * Bb + b_) * Hh + n0 + tx * 8;
#pragma unroll
        for (int j = 0; j < 4; j++) {
            float lo, hi;
            unpk2(acc2[i][j], lo, hi);
            int hcol = n0 + tx * 8 + 2 * j;
            float v0 = lo + bias[hcol];
            float v1 = hi + bias[hcol + 1];
            if (gate == 3) { v0 = tanhf(v0); v1 = tanhf(v1); }
            dst[2 * j]     = v0;
            dst[2 * j + 1] = v1;
        }
    }
}

// ---------------- persistent recurrence: all 512 steps in ONE kernel ----------------
// 128 blocks x 384 threads. Block owns h-tile [h0, h0+8) for gates f,i,o over all 64 b.
// SMEM: weights (3x8x1024, loaded once), ct chunk (64x128, double-clocked via reg
// prefetch), r results (24x64). One grid barrier per step.
//
// SMEM pitches (bank-conflict checked vs 128B bank span):
//   Ws pitch 1028 floats (4112B): h-lane offsets h*16 mod 128 -> distinct, x4 bcast
//   cts pitch 132 floats (528B): bs-lane offsets bs*16 mod 128 -> distinct, x8 bcast
#define WS_PITCH 1028
#define CT_PITCH 132
#define RS_PITCH 68
#define SMEM_FLOATS (24 * WS_PITCH + 64 * CT_PITCH + 24 * RS_PITCH)

__global__ __launch_bounds__(TPB, 1) void rec_persist_kernel(
    const float* __restrict__ Wcf, const float* __restrict__ Wci,
    const float* __restrict__ Wco, const float* __restrict__ c0,
    float* __restrict__ out, int write_tail) {
    extern __shared__ float sm[];
    float* Ws  = sm;                        // [24][1028]
    float* cts = Ws + 24 * WS_PITCH;        // [64][132]
    float* rs  = cts + 64 * CT_PITCH;       // [24][68]

    int tid = threadIdx.x;
    int h0 = blockIdx.x * 8;

    // ---- preload recurrent weights into SMEM (once per launch) ----
    {
        const float* Wg0 = Wcf;  const float* Wg1 = Wci;  const float* Wg2 = Wco;
#pragma unroll 1
        for (int col = 0; col < 24; col++) {
            const float* src = ((col >> 3) == 0 ? Wg0 : (col >> 3) == 1 ? Wg1 : Wg2)
                               + (size_t)(h0 + (col & 7)) * Hh;
            float4* dst = (float4*)(Ws + col * WS_PITCH);
            for (int k = tid; k < Hh / 4; k += TPB)
                dst[k] = ((const float4*)src)[k];
        }
    }

    int w = tid >> 5, lane = tid & 31;
    int bq = w & 3;                  // batch quarter (16 b)
    int hl = lane >> 2, bs = lane & 3;
    int col = (w >> 2) * 8 + hl;     // gate*8 + h_local
    const float* wrow = Ws + col * WS_PITCH;

    // ---- register-carried cell state for pointwise threads ----
    float creg0 = 0.f, creg1 = 0.f;
    int pb = tid >> 2, phq = tid & 3;     // pointwise: batch, h-quarter (2 h each)
    if (tid < 256) {
        creg0 = c0[h0 + phq * 2 + 0];
        creg1 = c0[h0 + phq * 2 + 1];
    }
    __syncthreads();

    float4 pf[8];
    for (int t = 0; t < Tt; t++) {
        const float* ct_in = ct_buf[t & 1];
        float* ct_out = ct_buf[(t & 1) ^ 1];

        ull acc[4] = {0ull, 0ull, 0ull, 0ull};

        // prefetch ct chunk 0 (L2-only loads: ct written by other SMs)
        if (tid < 256) {
#pragma unroll
            for (int i = 0; i < 8; i++) {
                int j = i * 256 + tid;
                pf[i] = __ldcg((const float4*)ct_in + (j >> 5) * (Hh / 4) + (j & 31));
            }
        }

#pragma unroll 1
        for (int c = 0; c < 8; c++) {
            __syncthreads();
            if (tid < 256) {
#pragma unroll
                for (int i = 0; i < 8; i++) {
                    int j = i * 256 + tid;
                    *(float4*)(cts + (j >> 5) * CT_PITCH + (j & 31) * 4) = pf[i];
                }
            }
            __syncthreads();
            if (c < 7 && tid < 256) {
                int kc4 = (c + 1) * 32;
#pragma unroll
                for (int i = 0; i < 8; i++) {
                    int j = i * 256 + tid;
                    pf[i] = __ldcg((const float4*)ct_in + (j >> 5) * (Hh / 4) + kc4 + (j & 31));
                }
            }
            // compute this chunk: 32 k-quads
#pragma unroll 8
            for (int k4 = 0; k4 < 32; k4++) {
                ulonglong2 wv = *(const ulonglong2*)(wrow + c * 128 + k4 * 4);
#pragma unroll
                for (int bi = 0; bi < 4; bi++) {
                    int b = bq * 16 + bi * 4 + bs;
                    ulonglong2 cv = *(const ulonglong2*)(cts + b * CT_PITCH + k4 * 4);
                    fma2(acc[bi], cv.x, wv.x);
                    fma2(acc[bi], cv.y, wv.y);
                }
            }
        }

        // write r results to SMEM
#pragma unroll
        for (int bi = 0; bi < 4; bi++) {
            float lo, hi;
            unpk2(acc[bi], lo, hi);
            rs[col * RS_PITCH + bq * 16 + bi * 4 + bs] = lo + hi;
        }
        __syncthreads();

        // ---- pointwise LSTM update (block-local: all 3 gates present) ----
        if (tid < 256) {
#pragma unroll
            for (int hh = 0; hh < 2; hh++) {
                int hl2 = phq * 2 + hh;
                int hg = h0 + hl2;
                size_t gb = (size_t)t * Bb * Hh + (size_t)pb * Hh + hg;
                float gf = g_pre[gb];
                float gi = g_pre[(size_t)Tt * Bb * Hh + gb];
                float go = g_pre[2ull * Tt * Bb * Hh + gb];
                float tc = g_pre[3ull * Tt * Bb * Hh + gb];   // pre-tanh'd
                float rf = rs[(0 * 8 + hl2) * RS_PITCH + pb];
                float ri = rs[(1 * 8 + hl2) * RS_PITCH + pb];
                float ro = rs[(2 * 8 + hl2) * RS_PITCH + pb];
                float cprev = hh ? creg1 : creg0;
                float f  = 1.f / (1.f + __expf(-(gf + rf)));
                float ii = 1.f / (1.f + __expf(-(gi + ri)));
                float o  = 1.f / (1.f + __expf(-(go + ro)));
                float cn = f * cprev + ii * tc;
                float hv = o * tanhf(cn);
                if (hh) creg1 = cn; else creg0 = cn;
                ct_out[pb * Hh + hg] = cn;
                out[((size_t)pb * Tt + t) * Hh + hg] = hv;
                if (write_tail && t == Tt - 1)
                    out[(size_t)Bb * Tt * Hh + pb * Hh + hg] = hv;
            }
        }

        // ---- grid barrier: all ct_out writes visible before next step ----
        __syncthreads();
        __threadfence();
        if (tid == 0) {
            atomicAdd(&g_bar, 1u);    // result unused -> RED (no-return)
            unsigned target = (unsigned)(t + 1) * NB;
            while (*((volatile unsigned*)&g_bar) < target) { }
        }
        __syncthreads();
        __threadfence();              // gpu-scope fence: CCTL.IVALL (L1 invalidate)
    }
}

// ---------------- launch ----------------
extern "C" void kernel_launch(void* const* d_in, const int* in_sizes, int n_in,
                              void* d_out, int out_size) {
    const float* x   = (const float*)d_in[0];
    const float* Wxf = (const float*)d_in[1];
    const float* Wcf = (const float*)d_in[2];
    const float* bcf = (const float*)d_in[3];
    const float* Wxi = (const float*)d_in[4];
    const float* Wci = (const float*)d_in[5];
    const float* bci = (const float*)d_in[6];
    const float* Wxo = (const float*)d_in[7];
    const float* Wco = (const float*)d_in[8];
    const float* bco = (const float*)d_in[9];
    const float* Wxc = (const float*)d_in[10];
    const float* bxc = (const float*)d_in[11];
    const float* c0  = (const float*)d_in[12];
    float* out = (float*)d_out;
    int write_tail = (out_size >= Bb * Tt * Hh + Bb * Hh) ? 1 : 0;

    static int smem_set = 0;
    if (!smem_set) {
        cudaFuncSetAttribute(rec_persist_kernel,
                             cudaFuncAttributeMaxDynamicSharedMemorySize,
                             SMEM_FLOATS * (int)sizeof(float));
        smem_set = 1;
    }

    init_kernel<<<256, 256>>>(c0);
    proj_kernel<<<dim3(256, 32), 256>>>(x, Wxf, Wxi, Wxo, Wxc, bcf, bci, bco, bxc);
    rec_persist_kernel<<<NB, TPB, SMEM_FLOATS * sizeof(float)>>>(
        Wcf, Wci, Wco, c0, out, write_tail);
}